// round 1
// baseline (speedup 1.0000x reference)
#include <cuda_runtime.h>
#include <math.h>

#define BB 4
#define SS 1024
#define DM 1280
#define NH 16
#define DK 80
#define GR 5
#define CPG 256

// ---- scratch (device globals; no allocations allowed) ----
__device__ float g_q[(size_t)BB*NH*SS*DK];
__device__ float g_k[(size_t)BB*NH*SS*DK];
__device__ float g_v[(size_t)BB*NH*SS*DK];
__device__ float g_att[(size_t)BB*SS*DM];

// ============================================================
// Kernel 1: channel shuffle + per-head QKV projections
// grid (S/64, H, B), block 256
// ============================================================
__global__ __launch_bounds__(256) void qkv_kernel(
    const float* __restrict__ src,
    const float* __restrict__ Wq, const float* __restrict__ bq,
    const float* __restrict__ Wk, const float* __restrict__ bk,
    const float* __restrict__ Wv, const float* __restrict__ bv)
{
    __shared__ float sW[DK*DK];
    __shared__ float sX[64][DK+1];
    __shared__ float sb[DK];
    const int b = blockIdx.z, h = blockIdx.y, s0 = blockIdx.x * 64;
    const int tid = threadIdx.x;

    // load X tile with channel shuffle fused:
    // x[b,s,d] = src[b,s,(d%5)*256 + d/5], d = h*80+e
    for (int i = tid; i < 64*DK; i += 256) {
        int r = i / DK, e = i % DK;
        int d = h*DK + e;
        sX[r][e] = src[((size_t)b*SS + s0 + r)*DM + (d % GR)*CPG + d/GR];
    }

    const float* Ws[3] = {Wq, Wk, Wv};
    const float* bs[3] = {bq, bk, bv};
    float* outs[3] = {g_q, g_k, g_v};

    for (int t = 0; t < 3; t++) {
        __syncthreads();   // protects sX (t=0) / sW reuse (t>0)
        for (int i = tid; i < DK*DK; i += 256) sW[i] = Ws[t][h*DK*DK + i];
        if (tid < DK) sb[tid] = bs[t][h*DK + tid];
        __syncthreads();
        for (int i = tid; i < 64*DK; i += 256) {
            int r = i / DK, e = i % DK;
            float a = sb[e];
            const float* wrow = &sW[e*DK];
            #pragma unroll 8
            for (int k = 0; k < DK; k++) a += wrow[k] * sX[r][k];
            outs[t][(((size_t)b*NH + h)*SS + s0 + r)*DK + e] = a;
        }
    }
}

// ============================================================
// Kernel 2: flash attention, one block per (b,h,64-row q tile)
// block 256 = 16(ty: 4 rows each) x 16(tx: 4 score cols / 5 out cols)
// dynamic smem ~77 KB
// ============================================================
__global__ __launch_bounds__(256) void attn_kernel()
{
    extern __shared__ float sm[];
    float* sQ = sm;                  // [80][65] transposed
    float* sK = sQ + 80*65;          // [80][65] transposed
    float* sV = sK + 80*65;          // [64][81]
    float* sP = sV + 64*81;          // [64][65] transposed (kk-major)

    const int b = blockIdx.z, h = blockIdx.y, q0 = blockIdx.x * 64;
    const int tid = threadIdx.x;
    const int ty = tid >> 4, tx = tid & 15;

    const size_t base = ((size_t)b*NH + h) * SS * DK;
    const float* Qb = g_q + base;
    const float* Kb = g_k + base;
    const float* Vb = g_v + base;

    for (int i = tid; i < 64*DK; i += 256) {
        int r = i / DK, k = i % DK;
        sQ[k*65 + r] = Qb[(size_t)(q0 + r)*DK + k];
    }

    float O[4][5], m_[4], l_[4];
    #pragma unroll
    for (int i = 0; i < 4; i++) {
        m_[i] = -1e30f; l_[i] = 0.f;
        #pragma unroll
        for (int c = 0; c < 5; c++) O[i][c] = 0.f;
    }
    const float scale = rsqrtf((float)DK);

    for (int kt = 0; kt < SS; kt += 64) {
        __syncthreads();   // previous PV done before overwriting sK/sV
        for (int i = tid; i < 64*DK; i += 256) {
            int r = i / DK, k = i % DK;
            sK[k*65 + r] = Kb[(size_t)(kt + r)*DK + k];
            sV[r*81 + k] = Vb[(size_t)(kt + r)*DK + k];
        }
        __syncthreads();

        // scores: 4x4 register tile
        float acc[4][4];
        #pragma unroll
        for (int i = 0; i < 4; i++)
            #pragma unroll
            for (int j = 0; j < 4; j++) acc[i][j] = 0.f;

        #pragma unroll 4
        for (int k = 0; k < DK; k++) {
            float qv[4], kv[4];
            #pragma unroll
            for (int i = 0; i < 4; i++) qv[i] = sQ[k*65 + ty*4 + i];
            #pragma unroll
            for (int j = 0; j < 4; j++) kv[j] = sK[k*65 + tx*4 + j];
            #pragma unroll
            for (int i = 0; i < 4; i++)
                #pragma unroll
                for (int j = 0; j < 4; j++)
                    acc[i][j] += qv[i] * kv[j];
        }

        // online softmax (row groups = 16 lanes sharing ty)
        #pragma unroll
        for (int i = 0; i < 4; i++) {
            float rmax = -1e30f;
            #pragma unroll
            for (int j = 0; j < 4; j++) {
                acc[i][j] *= scale;
                rmax = fmaxf(rmax, acc[i][j]);
            }
            #pragma unroll
            for (int msk = 8; msk; msk >>= 1)
                rmax = fmaxf(rmax, __shfl_xor_sync(0xffffffffu, rmax, msk));
            float mnew = fmaxf(m_[i], rmax);
            float alpha = __expf(m_[i] - mnew);
            m_[i] = mnew;
            float rsum = 0.f;
            #pragma unroll
            for (int j = 0; j < 4; j++) {
                float p = __expf(acc[i][j] - mnew);
                acc[i][j] = p;
                rsum += p;
            }
            #pragma unroll
            for (int msk = 8; msk; msk >>= 1)
                rsum += __shfl_xor_sync(0xffffffffu, rsum, msk);
            l_[i] = l_[i]*alpha + rsum;
            #pragma unroll
            for (int c = 0; c < 5; c++) O[i][c] *= alpha;
        }

        // stage P transposed for PV
        #pragma unroll
        for (int i = 0; i < 4; i++)
            #pragma unroll
            for (int j = 0; j < 4; j++)
                sP[(tx*4 + j)*65 + ty*4 + i] = acc[i][j];
        __syncthreads();

        // PV: 4 rows x 5 cols register tile
        #pragma unroll 2
        for (int kk = 0; kk < 64; kk++) {
            float pv[4], vv[5];
            #pragma unroll
            for (int i = 0; i < 4; i++) pv[i] = sP[kk*65 + ty*4 + i];
            #pragma unroll
            for (int c = 0; c < 5; c++) vv[c] = sV[kk*81 + tx*5 + c];
            #pragma unroll
            for (int i = 0; i < 4; i++)
                #pragma unroll
                for (int c = 0; c < 5; c++)
                    O[i][c] += pv[i] * vv[c];
        }
    }

    // epilogue: normalize + write concat layout [b, s, h*80 + e]
    #pragma unroll
    for (int i = 0; i < 4; i++) {
        float inv = 1.f / l_[i];
        int s = q0 + ty*4 + i;
        #pragma unroll
        for (int c = 0; c < 5; c++)
            g_att[((size_t)b*SS + s)*DM + h*DK + tx*5 + c] = O[i][c] * inv;
    }
}

// ============================================================
// Kernel 3: output projection GEMM  out = g_att @ Wo^T + bo
// M=4096, N=1280, K=1280; 128x128x16 tiles, 8x8 micro-tiles
// ============================================================
#define GM 128
#define GN 128
#define GK 16
__global__ __launch_bounds__(256) void out_gemm(
    const float* __restrict__ Wo, const float* __restrict__ bo,
    float* __restrict__ out)
{
    __shared__ float sA[GK][GM+1];
    __shared__ float sB[GK][GN+1];
    const int m0 = blockIdx.y * GM, n0 = blockIdx.x * GN;
    const int tid = threadIdx.x;
    const int ty = tid >> 4, tx = tid & 15;

    float acc[8][8];
    #pragma unroll
    for (int i = 0; i < 8; i++)
        #pragma unroll
        for (int j = 0; j < 8; j++) acc[i][j] = 0.f;

    for (int k0 = 0; k0 < DM; k0 += GK) {
        __syncthreads();
        for (int i = tid; i < GM*GK; i += 256) {
            int r = i >> 4, k = i & 15;
            sA[k][r] = g_att[(size_t)(m0 + r)*DM + k0 + k];
        }
        for (int i = tid; i < GN*GK; i += 256) {
            int r = i >> 4, k = i & 15;
            sB[k][r] = Wo[(size_t)(n0 + r)*DM + k0 + k];
        }
        __syncthreads();
        #pragma unroll
        for (int k = 0; k < GK; k++) {
            float a[8], bv[8];
            #pragma unroll
            for (int i = 0; i < 8; i++) a[i] = sA[k][ty*8 + i];
            #pragma unroll
            for (int j = 0; j < 8; j++) bv[j] = sB[k][tx*8 + j];
            #pragma unroll
            for (int i = 0; i < 8; i++)
                #pragma unroll
                for (int j = 0; j < 8; j++)
                    acc[i][j] += a[i] * bv[j];
        }
    }

    #pragma unroll
    for (int i = 0; i < 8; i++) {
        int m = m0 + ty*8 + i;
        #pragma unroll
        for (int j = 0; j < 8; j++) {
            int n = n0 + tx*8 + j;
            out[(size_t)m*DM + n] = acc[i][j] + bo[n];
        }
    }
}

// ============================================================
extern "C" void kernel_launch(void* const* d_in, const int* in_sizes, int n_in,
                              void* d_out, int out_size)
{
    const float* src = (const float*)d_in[0];
    // d_in[1] (k) and d_in[2] (v) are ignored by the reference module
    const float* Wq = (const float*)d_in[3];
    const float* bq = (const float*)d_in[4];
    const float* Wk = (const float*)d_in[5];
    const float* bk = (const float*)d_in[6];
    const float* Wv = (const float*)d_in[7];
    const float* bv = (const float*)d_in[8];
    const float* Wo = (const float*)d_in[9];
    const float* bo = (const float*)d_in[10];
    float* out = (float*)d_out;

    const int smem_attn = (80*65 + 80*65 + 64*81 + 64*65) * (int)sizeof(float);
    cudaFuncSetAttribute(attn_kernel, cudaFuncAttributeMaxDynamicSharedMemorySize, smem_attn);

    qkv_kernel<<<dim3(SS/64, NH, BB), 256>>>(src, Wq, bq, Wk, bk, Wv, bv);
    attn_kernel<<<dim3(SS/64, NH, BB), 256, smem_attn>>>();
    out_gemm<<<dim3(DM/GN, (BB*SS)/GM), 256>>>(Wo, bo, out);
}

// round 2
// speedup vs baseline: 1.5674x; 1.5674x over previous
#include <cuda_runtime.h>
#include <math.h>

#define BB 4
#define SS 1024
#define DM 1280
#define NH 16
#define DK 80
#define GR 5
#define CPG 256

// ---- scratch (device globals; no allocations allowed) ----
__device__ float g_q[(size_t)BB*NH*SS*DK];
__device__ float g_k[(size_t)BB*NH*SS*DK];
__device__ float g_v[(size_t)BB*NH*SS*DK];
__device__ float g_att[(size_t)BB*SS*DM];

// ============================================================
// Kernel 1: channel shuffle + per-head QKV projections
// grid (S/64, H, B), block 256 = 16x16, micro-tile 4 rows x 5 cols
// smem k-major + padded: conflict-free, vectorized row loads
// ============================================================
__global__ __launch_bounds__(256) void qkv_kernel(
    const float* __restrict__ src,
    const float* __restrict__ Wq, const float* __restrict__ bq,
    const float* __restrict__ Wk, const float* __restrict__ bk,
    const float* __restrict__ Wv, const float* __restrict__ bv)
{
    __shared__ float sX[DK][68];   // [k][r]  (k = input chan, r = row)
    __shared__ float sW[DK][84];   // [k][e]  (e = output chan)
    __shared__ float sb[DK];
    const int b = blockIdx.z, h = blockIdx.y, s0 = blockIdx.x * 64;
    const int tid = threadIdx.x;
    const int ty = tid >> 4, tx = tid & 15;

    // load X tile with channel shuffle fused, stored k-major:
    // x[d] = src[(d%5)*256 + d/5], d = h*80+k  ->  (k%5)*256 + 16h + k/5
    for (int i = tid; i < 64*DK; i += 256) {
        int k = i % DK, r = i / DK;
        sX[k][r] = src[((size_t)b*SS + s0 + r)*DM + (k % GR)*CPG + 16*h + k/GR];
    }

    const float* Ws[3] = {Wq, Wk, Wv};
    const float* bs[3] = {bq, bk, bv};
    float* outs[3] = {g_q, g_k, g_v};

    for (int t = 0; t < 3; t++) {
        __syncthreads();   // sX ready (t=0) / prev pass done with sW (t>0)
        for (int i = tid; i < DK*DK; i += 256) {
            int k = i % DK, e = i / DK;          // coalesced global read
            sW[k][e] = Ws[t][h*DK*DK + e*DK + k]; // store transposed [k][e]
        }
        if (tid < DK) sb[tid] = bs[t][h*DK + tid];
        __syncthreads();

        float acc[4][5];
        #pragma unroll
        for (int i = 0; i < 4; i++)
            #pragma unroll
            for (int c = 0; c < 5; c++) acc[i][c] = 0.f;

        #pragma unroll 4
        for (int k = 0; k < DK; k++) {
            float4 xv = *(const float4*)&sX[k][ty*4];
            float wv[5];
            #pragma unroll
            for (int c = 0; c < 5; c++) wv[c] = sW[k][tx*5 + c];
            float xr[4] = {xv.x, xv.y, xv.z, xv.w};
            #pragma unroll
            for (int i = 0; i < 4; i++)
                #pragma unroll
                for (int c = 0; c < 5; c++)
                    acc[i][c] += xr[i] * wv[c];
        }

        float* outp = outs[t] + (((size_t)b*NH + h)*SS + s0) * DK;
        #pragma unroll
        for (int i = 0; i < 4; i++)
            #pragma unroll
            for (int c = 0; c < 5; c++)
                outp[(size_t)(ty*4 + i)*DK + tx*5 + c] = acc[i][c] + sb[tx*5 + c];
    }
}

// ============================================================
// Kernel 2: flash attention, one block per (b,h,64-row q tile)
// block 256 = 16(ty: 4 rows) x 16(tx: 4 score cols / 5 out cols)
// ============================================================
#define PQK 68
#define PV_ 84
#define PP 68
__global__ __launch_bounds__(256) void attn_kernel()
{
    extern __shared__ float sm[];
    float* sQ = sm;                    // [80][PQK] transposed
    float* sK = sQ + DK*PQK;           // [80][PQK] transposed
    float* sV = sK + DK*PQK;           // [64][PV_]
    float* sP = sV + 64*PV_;           // [64][PP] (kk-major)

    const int b = blockIdx.z, h = blockIdx.y, q0 = blockIdx.x * 64;
    const int tid = threadIdx.x;
    const int ty = tid >> 4, tx = tid & 15;

    const size_t base = ((size_t)b*NH + h) * SS * DK;
    const float* Qb = g_q + base;
    const float* Kb = g_k + base;
    const float* Vb = g_v + base;

    for (int i = tid; i < 64*DK; i += 256) {
        int k = i % DK, r = i / DK;
        sQ[k*PQK + r] = Qb[(size_t)(q0 + r)*DK + k];
    }

    float O[4][5], m_[4], l_[4];
    #pragma unroll
    for (int i = 0; i < 4; i++) {
        m_[i] = -1e30f; l_[i] = 0.f;
        #pragma unroll
        for (int c = 0; c < 5; c++) O[i][c] = 0.f;
    }
    const float scale = rsqrtf((float)DK);

    for (int kt = 0; kt < SS; kt += 64) {
        __syncthreads();   // previous PV done before overwriting sK/sV
        for (int i = tid; i < 64*DK; i += 256) {
            int k = i % DK, r = i / DK;
            float kvv = Kb[(size_t)(kt + r)*DK + k];
            float vvv = Vb[(size_t)(kt + r)*DK + k];
            sK[k*PQK + r] = kvv;
            sV[r*PV_ + k] = vvv;
        }
        __syncthreads();

        // scores: 4x4 register tile, vectorized smem reads
        float acc[4][4];
        #pragma unroll
        for (int i = 0; i < 4; i++)
            #pragma unroll
            for (int j = 0; j < 4; j++) acc[i][j] = 0.f;

        #pragma unroll 4
        for (int k = 0; k < DK; k++) {
            float4 q4 = *(const float4*)&sQ[k*PQK + ty*4];
            float4 k4 = *(const float4*)&sK[k*PQK + tx*4];
            float qv[4] = {q4.x, q4.y, q4.z, q4.w};
            float kv[4] = {k4.x, k4.y, k4.z, k4.w};
            #pragma unroll
            for (int i = 0; i < 4; i++)
                #pragma unroll
                for (int j = 0; j < 4; j++)
                    acc[i][j] += qv[i] * kv[j];
        }

        // online softmax (16-lane row groups share ty)
        #pragma unroll
        for (int i = 0; i < 4; i++) {
            float rmax = -1e30f;
            #pragma unroll
            for (int j = 0; j < 4; j++) {
                acc[i][j] *= scale;
                rmax = fmaxf(rmax, acc[i][j]);
            }
            #pragma unroll
            for (int msk = 8; msk; msk >>= 1)
                rmax = fmaxf(rmax, __shfl_xor_sync(0xffffffffu, rmax, msk));
            float mnew = fmaxf(m_[i], rmax);
            float alpha = __expf(m_[i] - mnew);
            m_[i] = mnew;
            float rsum = 0.f;
            #pragma unroll
            for (int j = 0; j < 4; j++) {
                float p = __expf(acc[i][j] - mnew);
                acc[i][j] = p;
                rsum += p;
            }
            #pragma unroll
            for (int msk = 8; msk; msk >>= 1)
                rsum += __shfl_xor_sync(0xffffffffu, rsum, msk);
            l_[i] = l_[i]*alpha + rsum;
            #pragma unroll
            for (int c = 0; c < 5; c++) O[i][c] *= alpha;
        }

        // stage P (kk-major) for PV
        #pragma unroll
        for (int i = 0; i < 4; i++)
            #pragma unroll
            for (int j = 0; j < 4; j++)
                sP[(tx*4 + j)*PP + ty*4 + i] = acc[i][j];
        __syncthreads();

        // PV: 4 rows x 5 cols register tile
        #pragma unroll 2
        for (int kk = 0; kk < 64; kk++) {
            float4 p4 = *(const float4*)&sP[kk*PP + ty*4];
            float pv[4] = {p4.x, p4.y, p4.z, p4.w};
            float vv[5];
            #pragma unroll
            for (int c = 0; c < 5; c++) vv[c] = sV[kk*PV_ + tx*5 + c];
            #pragma unroll
            for (int i = 0; i < 4; i++)
                #pragma unroll
                for (int c = 0; c < 5; c++)
                    O[i][c] += pv[i] * vv[c];
        }
    }

    // epilogue: normalize + write concat layout [b, s, h*80 + e]
    #pragma unroll
    for (int i = 0; i < 4; i++) {
        float inv = 1.f / l_[i];
        int s = q0 + ty*4 + i;
        #pragma unroll
        for (int c = 0; c < 5; c++)
            g_att[((size_t)b*SS + s)*DM + h*DK + tx*5 + c] = O[i][c] * inv;
    }
}

// ============================================================
// Kernel 3: output projection GEMM  out = g_att @ Wo^T + bo
// M=4096, N=1280, K=1280; 128x128x16 tiles, 8x8 micro-tiles
// ============================================================
#define GM 128
#define GN 128
#define GK 16
#define GP 132
__global__ __launch_bounds__(256) void out_gemm(
    const float* __restrict__ Wo, const float* __restrict__ bo,
    float* __restrict__ out)
{
    __shared__ float sA[GK][GP];
    __shared__ float sB[GK][GP];
    const int m0 = blockIdx.y * GM, n0 = blockIdx.x * GN;
    const int tid = threadIdx.x;
    const int ty = tid >> 4, tx = tid & 15;

    float acc[8][8];
    #pragma unroll
    for (int i = 0; i < 8; i++)
        #pragma unroll
        for (int j = 0; j < 8; j++) acc[i][j] = 0.f;

    for (int k0 = 0; k0 < DM; k0 += GK) {
        __syncthreads();
        for (int i = tid; i < GM*GK; i += 256) {
            int r = i >> 4, k = i & 15;
            sA[k][r] = g_att[(size_t)(m0 + r)*DM + k0 + k];
        }
        for (int i = tid; i < GN*GK; i += 256) {
            int r = i >> 4, k = i & 15;
            sB[k][r] = Wo[(size_t)(n0 + r)*DM + k0 + k];
        }
        __syncthreads();
        #pragma unroll
        for (int k = 0; k < GK; k++) {
            float4 a0 = *(const float4*)&sA[k][ty*8];
            float4 a1 = *(const float4*)&sA[k][ty*8 + 4];
            float4 b0 = *(const float4*)&sB[k][tx*8];
            float4 b1 = *(const float4*)&sB[k][tx*8 + 4];
            float a[8] = {a0.x,a0.y,a0.z,a0.w,a1.x,a1.y,a1.z,a1.w};
            float bv[8] = {b0.x,b0.y,b0.z,b0.w,b1.x,b1.y,b1.z,b1.w};
            #pragma unroll
            for (int i = 0; i < 8; i++)
                #pragma unroll
                for (int j = 0; j < 8; j++)
                    acc[i][j] += a[i] * bv[j];
        }
    }

    #pragma unroll
    for (int i = 0; i < 8; i++) {
        int m = m0 + ty*8 + i;
        #pragma unroll
        for (int j = 0; j < 8; j++) {
            int n = n0 + tx*8 + j;
            out[(size_t)m*DM + n] = acc[i][j] + bo[n];
        }
    }
}

// ============================================================
extern "C" void kernel_launch(void* const* d_in, const int* in_sizes, int n_in,
                              void* d_out, int out_size)
{
    const float* src = (const float*)d_in[0];
    // d_in[1] (k) and d_in[2] (v) are ignored by the reference module
    const float* Wq = (const float*)d_in[3];
    const float* bq = (const float*)d_in[4];
    const float* Wk = (const float*)d_in[5];
    const float* bk = (const float*)d_in[6];
    const float* Wv = (const float*)d_in[7];
    const float* bv = (const float*)d_in[8];
    const float* Wo = (const float*)d_in[9];
    const float* bo = (const float*)d_in[10];
    float* out = (float*)d_out;

    const int smem_attn = (DK*PQK + DK*PQK + 64*PV_ + 64*PP) * (int)sizeof(float);
    cudaFuncSetAttribute(attn_kernel, cudaFuncAttributeMaxDynamicSharedMemorySize, smem_attn);

    qkv_kernel<<<dim3(SS/64, NH, BB), 256>>>(src, Wq, bq, Wk, bk, Wv, bv);
    attn_kernel<<<dim3(SS/64, NH, BB), 256, smem_attn>>>();
    out_gemm<<<dim3(DM/GN, (BB*SS)/GM), 256>>>(Wo, bo, out);
}

// round 3
// speedup vs baseline: 2.7862x; 1.7776x over previous
#include <cuda_runtime.h>
#include <math.h>

#define BB 4
#define SS 1024
#define DM 1280
#define NH 16
#define DK 80
#define GR 5
#define CPG 256

// ---- scratch (device globals; no allocations allowed) ----
__device__ float g_q[(size_t)BB*NH*SS*DK];
__device__ float g_k[(size_t)BB*NH*SS*DK];
__device__ float g_v[(size_t)BB*NH*SS*DK];
__device__ float g_att[(size_t)BB*SS*DM];

// ---- tf32 helpers ----
__device__ __forceinline__ float f2tf32(float x) {
    unsigned u;
    asm("cvt.rna.tf32.f32 %0, %1;" : "=r"(u) : "f"(x));
    return __uint_as_float(u);
}
__device__ __forceinline__ void mma_tf32(float d[4], const unsigned a[4], const unsigned b[2]) {
    asm volatile(
        "mma.sync.aligned.m16n8k8.row.col.f32.tf32.tf32.f32 "
        "{%0,%1,%2,%3}, {%4,%5,%6,%7}, {%8,%9}, {%0,%1,%2,%3};\n"
        : "+f"(d[0]), "+f"(d[1]), "+f"(d[2]), "+f"(d[3])
        : "r"(a[0]), "r"(a[1]), "r"(a[2]), "r"(a[3]), "r"(b[0]), "r"(b[1]));
}

// ============================================================
// Kernel 1: channel shuffle + per-head QKV projections (fp32)
// ============================================================
__global__ __launch_bounds__(256) void qkv_kernel(
    const float* __restrict__ src,
    const float* __restrict__ Wq, const float* __restrict__ bq,
    const float* __restrict__ Wk, const float* __restrict__ bk,
    const float* __restrict__ Wv, const float* __restrict__ bv)
{
    __shared__ float sX[DK][68];
    __shared__ float sW[DK][84];
    __shared__ float sb[DK];
    const int b = blockIdx.z, h = blockIdx.y, s0 = blockIdx.x * 64;
    const int tid = threadIdx.x;
    const int ty = tid >> 4, tx = tid & 15;

    for (int i = tid; i < 64*DK; i += 256) {
        int k = i % DK, r = i / DK;
        sX[k][r] = src[((size_t)b*SS + s0 + r)*DM + (k % GR)*CPG + 16*h + k/GR];
    }

    const float* Ws[3] = {Wq, Wk, Wv};
    const float* bs[3] = {bq, bk, bv};
    float* outs[3] = {g_q, g_k, g_v};

    for (int t = 0; t < 3; t++) {
        __syncthreads();
        for (int i = tid; i < DK*DK; i += 256) {
            int k = i % DK, e = i / DK;
            sW[k][e] = Ws[t][h*DK*DK + e*DK + k];
        }
        if (tid < DK) sb[tid] = bs[t][h*DK + tid];
        __syncthreads();

        float acc[4][5];
        #pragma unroll
        for (int i = 0; i < 4; i++)
            #pragma unroll
            for (int c = 0; c < 5; c++) acc[i][c] = 0.f;

        #pragma unroll 4
        for (int k = 0; k < DK; k++) {
            float4 xv = *(const float4*)&sX[k][ty*4];
            float wv[5];
            #pragma unroll
            for (int c = 0; c < 5; c++) wv[c] = sW[k][tx*5 + c];
            float xr[4] = {xv.x, xv.y, xv.z, xv.w};
            #pragma unroll
            for (int i = 0; i < 4; i++)
                #pragma unroll
                for (int c = 0; c < 5; c++)
                    acc[i][c] += xr[i] * wv[c];
        }

        float* outp = outs[t] + (((size_t)b*NH + h)*SS + s0) * DK;
        #pragma unroll
        for (int i = 0; i < 4; i++)
            #pragma unroll
            for (int c = 0; c < 5; c++)
                outp[(size_t)(ty*4 + i)*DK + tx*5 + c] = acc[i][c] + sb[tx*5 + c];
    }
}

// ============================================================
// Kernel 2: flash attention with tf32 mma.sync
// block 256 = 8 warps; each warp owns 16 q-rows of a 128-row tile
// kv tiles of 64. Q frags cached in regs; P via warp-private smem.
// ============================================================
#define QP 84
#define KP 84
#define VP 88
#define PP 68
// smem float offsets
#define OFF_Q 0
#define OFF_K (128*QP)
#define OFF_V (OFF_K + 64*KP)
#define OFF_P (OFF_V + 64*VP)
#define ATTN_SMEM_FLOATS (OFF_P + 128*PP)

__global__ __launch_bounds__(256, 1) void attn_kernel()
{
    extern __shared__ float sm[];
    float* sQ = sm + OFF_Q;
    float* sK = sm + OFF_K;
    float* sV = sm + OFF_V;
    float* sP = sm + OFF_P;

    const int b = blockIdx.z, h = blockIdx.y, q0 = blockIdx.x * 128;
    const int tid = threadIdx.x;
    const int warp = tid >> 5, lane = tid & 31;
    const int g = lane >> 2, t = lane & 3;
    const int wr = warp * 16;

    const size_t base = ((size_t)b*NH + h) * SS * DK;
    const float* Qb = g_q + base;
    const float* Kb = g_k + base;
    const float* Vb = g_v + base;

    const float scl = rsqrtf((float)DK);

    // load Q tile (scaled + tf32-rounded)
    for (int i = tid; i < 128*DK; i += 256) {
        int r = i / DK, k = i % DK;
        sQ[r*QP + k] = f2tf32(Qb[(size_t)(q0 + r)*DK + k] * scl);
    }
    __syncthreads();

    // cache Q A-fragments in registers (10 k-steps)
    unsigned qa[10][4];
    #pragma unroll
    for (int ks = 0; ks < 10; ks++) {
        qa[ks][0] = __float_as_uint(sQ[(wr + g    )*QP + ks*8 + t    ]);
        qa[ks][1] = __float_as_uint(sQ[(wr + g + 8)*QP + ks*8 + t    ]);
        qa[ks][2] = __float_as_uint(sQ[(wr + g    )*QP + ks*8 + t + 4]);
        qa[ks][3] = __float_as_uint(sQ[(wr + g + 8)*QP + ks*8 + t + 4]);
    }

    float O[10][4];
    #pragma unroll
    for (int nt = 0; nt < 10; nt++)
        #pragma unroll
        for (int j = 0; j < 4; j++) O[nt][j] = 0.f;
    float m0 = -1e30f, m1 = -1e30f, l0 = 0.f, l1 = 0.f;

    for (int kt = 0; kt < SS; kt += 64) {
        __syncthreads();   // prev PV done before K/V overwrite
        for (int i = tid; i < 64*DK; i += 256) {
            int r = i / DK, k = i % DK;
            sK[r*KP + k] = f2tf32(Kb[(size_t)(kt + r)*DK + k]);
            sV[r*VP + k] = f2tf32(Vb[(size_t)(kt + r)*DK + k]);
        }
        __syncthreads();

        // ---- scores: 16x64 per warp = 8 n-tiles ----
        float sc[8][4];
        #pragma unroll
        for (int nt = 0; nt < 8; nt++)
            #pragma unroll
            for (int j = 0; j < 4; j++) sc[nt][j] = 0.f;

        #pragma unroll
        for (int ks = 0; ks < 10; ks++) {
            #pragma unroll
            for (int nt = 0; nt < 8; nt++) {
                unsigned bb[2];
                bb[0] = __float_as_uint(sK[(nt*8 + g)*KP + ks*8 + t    ]);
                bb[1] = __float_as_uint(sK[(nt*8 + g)*KP + ks*8 + t + 4]);
                mma_tf32(sc[nt], qa[ks], bb);
            }
        }

        // ---- online softmax (rows g and g+8, warp-local) ----
        float mx0 = -1e30f, mx1 = -1e30f;
        #pragma unroll
        for (int nt = 0; nt < 8; nt++) {
            mx0 = fmaxf(mx0, fmaxf(sc[nt][0], sc[nt][1]));
            mx1 = fmaxf(mx1, fmaxf(sc[nt][2], sc[nt][3]));
        }
        #pragma unroll
        for (int msk = 1; msk <= 2; msk <<= 1) {
            mx0 = fmaxf(mx0, __shfl_xor_sync(0xffffffffu, mx0, msk));
            mx1 = fmaxf(mx1, __shfl_xor_sync(0xffffffffu, mx1, msk));
        }
        float mn0 = fmaxf(m0, mx0), mn1 = fmaxf(m1, mx1);
        float a0 = __expf(m0 - mn0), a1 = __expf(m1 - mn1);
        m0 = mn0; m1 = mn1;

        float sum0 = 0.f, sum1 = 0.f;
        #pragma unroll
        for (int nt = 0; nt < 8; nt++) {
            sc[nt][0] = __expf(sc[nt][0] - m0);
            sc[nt][1] = __expf(sc[nt][1] - m0);
            sc[nt][2] = __expf(sc[nt][2] - m1);
            sc[nt][3] = __expf(sc[nt][3] - m1);
            sum0 += sc[nt][0] + sc[nt][1];
            sum1 += sc[nt][2] + sc[nt][3];
        }
        #pragma unroll
        for (int msk = 1; msk <= 2; msk <<= 1) {
            sum0 += __shfl_xor_sync(0xffffffffu, sum0, msk);
            sum1 += __shfl_xor_sync(0xffffffffu, sum1, msk);
        }
        l0 = l0*a0 + sum0;
        l1 = l1*a1 + sum1;

        #pragma unroll
        for (int nt = 0; nt < 10; nt++) {
            O[nt][0] *= a0; O[nt][1] *= a0;
            O[nt][2] *= a1; O[nt][3] *= a1;
        }

        // ---- stage P (warp-private rows) ----
        #pragma unroll
        for (int nt = 0; nt < 8; nt++) {
            sP[(wr + g    )*PP + nt*8 + 2*t    ] = f2tf32(sc[nt][0]);
            sP[(wr + g    )*PP + nt*8 + 2*t + 1] = f2tf32(sc[nt][1]);
            sP[(wr + g + 8)*PP + nt*8 + 2*t    ] = f2tf32(sc[nt][2]);
            sP[(wr + g + 8)*PP + nt*8 + 2*t + 1] = f2tf32(sc[nt][3]);
        }
        __syncwarp();

        // ---- PV: O(16x80) += P(16x64) @ V(64x80) ----
        #pragma unroll
        for (int ks = 0; ks < 8; ks++) {
            unsigned pa[4];
            pa[0] = __float_as_uint(sP[(wr + g    )*PP + ks*8 + t    ]);
            pa[1] = __float_as_uint(sP[(wr + g + 8)*PP + ks*8 + t    ]);
            pa[2] = __float_as_uint(sP[(wr + g    )*PP + ks*8 + t + 4]);
            pa[3] = __float_as_uint(sP[(wr + g + 8)*PP + ks*8 + t + 4]);
            #pragma unroll
            for (int nt = 0; nt < 10; nt++) {
                unsigned bb[2];
                bb[0] = __float_as_uint(sV[(ks*8 + t    )*VP + nt*8 + g]);
                bb[1] = __float_as_uint(sV[(ks*8 + t + 4)*VP + nt*8 + g]);
                mma_tf32(O[nt], pa, bb);
            }
        }
    }

    // ---- epilogue ----
    float inv0 = 1.f / l0, inv1 = 1.f / l1;
    int s0r = q0 + wr + g, s1r = s0r + 8;
    #pragma unroll
    for (int nt = 0; nt < 10; nt++) {
        int c = nt*8 + 2*t;
        float2 v0 = make_float2(O[nt][0]*inv0, O[nt][1]*inv0);
        float2 v1 = make_float2(O[nt][2]*inv1, O[nt][3]*inv1);
        *(float2*)&g_att[((size_t)b*SS + s0r)*DM + h*DK + c] = v0;
        *(float2*)&g_att[((size_t)b*SS + s1r)*DM + h*DK + c] = v1;
    }
}

// ============================================================
// Kernel 3: out = g_att @ Wo^T + bo, 3xTF32 split for accuracy
// 128x128x16 tiles, 8 warps (2x4), warp tile 64x32
// ============================================================
#define OST 20
__global__ __launch_bounds__(256, 2) void out_gemm(
    const float* __restrict__ Wo, const float* __restrict__ bo,
    float* __restrict__ out)
{
    __shared__ float sAh[128*OST], sAl[128*OST];
    __shared__ float sBh[128*OST], sBl[128*OST];

    const int m0 = blockIdx.y * 128, n0 = blockIdx.x * 128;
    const int tid = threadIdx.x;
    const int warp = tid >> 5, lane = tid & 31;
    const int g = lane >> 2, t = lane & 3;
    const int wm = warp >> 2, wn = warp & 3;   // 2 x 4 warps

    float acc[4][4][4];
    #pragma unroll
    for (int mt = 0; mt < 4; mt++)
        #pragma unroll
        for (int nt = 0; nt < 4; nt++)
            #pragma unroll
            for (int j = 0; j < 4; j++) acc[mt][nt][j] = 0.f;

    // staging: each thread handles 2 float4 of A and 2 of B per chunk
    float4 ra[2], rb[2];
    #pragma unroll
    for (int p = 0; p < 2; p++) {
        int idx = tid + p*256;
        int r = idx >> 2, c = (idx & 3) * 4;
        ra[p] = *(const float4*)&g_att[(size_t)(m0 + r)*DM + c];
        rb[p] = *(const float4*)&Wo[(size_t)(n0 + r)*DM + c];
    }

    for (int kc = 0; kc < DM/16; kc++) {
        // split + store current chunk to smem
        #pragma unroll
        for (int p = 0; p < 2; p++) {
            int idx = tid + p*256;
            int r = idx >> 2, c = (idx & 3) * 4;
            float av[4] = {ra[p].x, ra[p].y, ra[p].z, ra[p].w};
            float bv[4] = {rb[p].x, rb[p].y, rb[p].z, rb[p].w};
            #pragma unroll
            for (int q = 0; q < 4; q++) {
                float ah = f2tf32(av[q]);
                float bh = f2tf32(bv[q]);
                sAh[r*OST + c + q] = ah;
                sAl[r*OST + c + q] = f2tf32(av[q] - ah);
                sBh[r*OST + c + q] = bh;
                sBl[r*OST + c + q] = f2tf32(bv[q] - bh);
            }
        }
        __syncthreads();

        // prefetch next chunk
        if (kc < DM/16 - 1) {
            int k0n = (kc + 1) * 16;
            #pragma unroll
            for (int p = 0; p < 2; p++) {
                int idx = tid + p*256;
                int r = idx >> 2, c = (idx & 3) * 4;
                ra[p] = *(const float4*)&g_att[(size_t)(m0 + r)*DM + k0n + c];
                rb[p] = *(const float4*)&Wo[(size_t)(n0 + r)*DM + k0n + c];
            }
        }

        // compute: 2 k-steps of 8
        #pragma unroll
        for (int kk = 0; kk < 2; kk++) {
            unsigned bh[4][2], bl[4][2];
            #pragma unroll
            for (int nt = 0; nt < 4; nt++) {
                int nrow = wn*32 + nt*8 + g;
                bh[nt][0] = __float_as_uint(sBh[nrow*OST + kk*8 + t    ]);
                bh[nt][1] = __float_as_uint(sBh[nrow*OST + kk*8 + t + 4]);
                bl[nt][0] = __float_as_uint(sBl[nrow*OST + kk*8 + t    ]);
                bl[nt][1] = __float_as_uint(sBl[nrow*OST + kk*8 + t + 4]);
            }
            #pragma unroll
            for (int mt = 0; mt < 4; mt++) {
                int mrow = wm*64 + mt*16;
                unsigned ah[4], al[4];
                ah[0] = __float_as_uint(sAh[(mrow + g    )*OST + kk*8 + t    ]);
                ah[1] = __float_as_uint(sAh[(mrow + g + 8)*OST + kk*8 + t    ]);
                ah[2] = __float_as_uint(sAh[(mrow + g    )*OST + kk*8 + t + 4]);
                ah[3] = __float_as_uint(sAh[(mrow + g + 8)*OST + kk*8 + t + 4]);
                al[0] = __float_as_uint(sAl[(mrow + g    )*OST + kk*8 + t    ]);
                al[1] = __float_as_uint(sAl[(mrow + g + 8)*OST + kk*8 + t    ]);
                al[2] = __float_as_uint(sAl[(mrow + g    )*OST + kk*8 + t + 4]);
                al[3] = __float_as_uint(sAl[(mrow + g + 8)*OST + kk*8 + t + 4]);
                #pragma unroll
                for (int nt = 0; nt < 4; nt++) {
                    mma_tf32(acc[mt][nt], ah, bh[nt]);
                    mma_tf32(acc[mt][nt], ah, bl[nt]);
                    mma_tf32(acc[mt][nt], al, bh[nt]);
                }
            }
        }
        __syncthreads();
    }

    // epilogue
    #pragma unroll
    for (int mt = 0; mt < 4; mt++) {
        int r0 = m0 + wm*64 + mt*16 + g;
        #pragma unroll
        for (int nt = 0; nt < 4; nt++) {
            int c0 = n0 + wn*32 + nt*8 + 2*t;
            float2 b2 = *(const float2*)&bo[c0];
            float2 v0 = make_float2(acc[mt][nt][0] + b2.x, acc[mt][nt][1] + b2.y);
            float2 v1 = make_float2(acc[mt][nt][2] + b2.x, acc[mt][nt][3] + b2.y);
            *(float2*)&out[(size_t)r0*DM + c0] = v0;
            *(float2*)&out[(size_t)(r0 + 8)*DM + c0] = v1;
        }
    }
}

// ============================================================
extern "C" void kernel_launch(void* const* d_in, const int* in_sizes, int n_in,
                              void* d_out, int out_size)
{
    const float* src = (const float*)d_in[0];
    const float* Wq = (const float*)d_in[3];
    const float* bq = (const float*)d_in[4];
    const float* Wk = (const float*)d_in[5];
    const float* bk = (const float*)d_in[6];
    const float* Wv = (const float*)d_in[7];
    const float* bv = (const float*)d_in[8];
    const float* Wo = (const float*)d_in[9];
    const float* bo = (const float*)d_in[10];
    float* out = (float*)d_out;

    const int smem_attn = ATTN_SMEM_FLOATS * (int)sizeof(float);
    cudaFuncSetAttribute(attn_kernel, cudaFuncAttributeMaxDynamicSharedMemorySize, smem_attn);

    qkv_kernel<<<dim3(SS/64, NH, BB), 256>>>(src, Wq, bq, Wk, bk, Wv, bv);
    attn_kernel<<<dim3(SS/128, NH, BB), 256, smem_attn>>>();
    out_gemm<<<dim3(DM/128, (BB*SS)/128), 256>>>(Wo, bo, out);
}

// round 4
// speedup vs baseline: 3.3480x; 1.2017x over previous
#include <cuda_runtime.h>
#include <math.h>

#define BB 4
#define SS 1024
#define DM 1280
#define NH 16
#define DK 80
#define GR 5
#define CPG 256

// ---- scratch (device globals; no allocations allowed) ----
__device__ float g_q[(size_t)BB*NH*SS*DK];
__device__ float g_k[(size_t)BB*NH*SS*DK];
__device__ float g_v[(size_t)BB*NH*SS*DK];
__device__ float g_att[(size_t)BB*SS*DM];

// ---- helpers ----
__device__ __forceinline__ float f2tf32(float x) {
    unsigned u;
    asm("cvt.rna.tf32.f32 %0, %1;" : "=r"(u) : "f"(x));
    return __uint_as_float(u);
}
__device__ __forceinline__ void mma_tf32(float d[4], const unsigned a[4], const unsigned b[2]) {
    asm volatile(
        "mma.sync.aligned.m16n8k8.row.col.f32.tf32.tf32.f32 "
        "{%0,%1,%2,%3}, {%4,%5,%6,%7}, {%8,%9}, {%0,%1,%2,%3};\n"
        : "+f"(d[0]), "+f"(d[1]), "+f"(d[2]), "+f"(d[3])
        : "r"(a[0]), "r"(a[1]), "r"(a[2]), "r"(a[3]), "r"(b[0]), "r"(b[1]));
}
__device__ __forceinline__ unsigned smem_u32(const void* p) {
    return (unsigned)__cvta_generic_to_shared(p);
}
__device__ __forceinline__ void cp16(unsigned s, const void* g) {
    asm volatile("cp.async.cg.shared.global [%0], [%1], 16;" :: "r"(s), "l"(g));
}
__device__ __forceinline__ void cp_commit() { asm volatile("cp.async.commit_group;"); }
template<int N> __device__ __forceinline__ void cp_wait() {
    asm volatile("cp.async.wait_group %0;" :: "n"(N));
}
// column pairing within 8-group: (t, t+4) -> adjacent (2t, 2t+1)
__device__ __forceinline__ int perm8(int c) {
    return (c & ~7) | ((c & 3) << 1) | ((c >> 2) & 1);
}

// ============================================================
// Kernel 1: channel shuffle + per-head QKV projections (fp32)
// 128 rows/block, micro-tile 8x5; outputs rna-rounded to tf32
// ============================================================
__global__ __launch_bounds__(256) void qkv_kernel(
    const float* __restrict__ src,
    const float* __restrict__ Wq, const float* __restrict__ bq,
    const float* __restrict__ Wk, const float* __restrict__ bk,
    const float* __restrict__ Wv, const float* __restrict__ bv)
{
    extern __shared__ float qsm[];
    float* sX = qsm;               // [80][132]  (k-major)
    float* sW = sX + DK*132;       // [80][84]   (k-major)
    float* sb = sW + DK*84;        // [80]

    const int b = blockIdx.z, h = blockIdx.y, s0 = blockIdx.x * 128;
    const int tid = threadIdx.x;
    const int ty = tid >> 4, tx = tid & 15;

    for (int i = tid; i < 128*DK; i += 256) {
        int k = i % DK, r = i / DK;
        sX[k*132 + r] = src[((size_t)b*SS + s0 + r)*DM + (k % GR)*CPG + 16*h + k/GR];
    }

    const float* Ws[3] = {Wq, Wk, Wv};
    const float* bs[3] = {bq, bk, bv};
    float* outs[3] = {g_q, g_k, g_v};

    for (int t = 0; t < 3; t++) {
        __syncthreads();
        for (int i = tid; i < DK*DK; i += 256) {
            int k = i % DK, e = i / DK;
            sW[k*84 + e] = Ws[t][h*DK*DK + e*DK + k];
        }
        if (tid < DK) sb[tid] = bs[t][h*DK + tid];
        __syncthreads();

        float acc[8][5];
        #pragma unroll
        for (int i = 0; i < 8; i++)
            #pragma unroll
            for (int c = 0; c < 5; c++) acc[i][c] = 0.f;

        #pragma unroll 4
        for (int k = 0; k < DK; k++) {
            float4 x0 = *(const float4*)&sX[k*132 + ty*8];
            float4 x1 = *(const float4*)&sX[k*132 + ty*8 + 4];
            float xr[8] = {x0.x,x0.y,x0.z,x0.w,x1.x,x1.y,x1.z,x1.w};
            float wv[5];
            #pragma unroll
            for (int c = 0; c < 5; c++) wv[c] = sW[k*84 + tx*5 + c];
            #pragma unroll
            for (int i = 0; i < 8; i++)
                #pragma unroll
                for (int c = 0; c < 5; c++)
                    acc[i][c] += xr[i] * wv[c];
        }

        float* outp = outs[t] + (((size_t)b*NH + h)*SS + s0) * DK;
        #pragma unroll
        for (int i = 0; i < 8; i++)
            #pragma unroll
            for (int c = 0; c < 5; c++)
                outp[(size_t)(ty*8 + i)*DK + tx*5 + c] = f2tf32(acc[i][c] + sb[tx*5 + c]);
    }
}

// ============================================================
// Kernel 2: flash attention, tf32 mma, cp.async double-buffered
// block 256 = 8 warps x 16 q-rows; 128-row q tiles, 64-row kv tiles
// sP overlays sQ; K stride 84, V stride 88, Q/P stride 88 (paired cols)
// ============================================================
#define QP 88
#define KP 84
#define VP 88
#define OFF_Q 0
#define OFF_K (128*QP)
#define OFF_V (OFF_K + 2*64*KP)
#define ATTN_SMEM_FLOATS (OFF_V + 2*64*VP)

__device__ __forceinline__ void attn_issue(const float* Kb, const float* Vb,
                                           float* sK, float* sV, int kt, int tid)
{
    #pragma unroll
    for (int p = 0; p < 5; p++) {
        int c = tid + p*256;
        int r = c / 20, seg = c % 20;
        cp16(smem_u32(sK + r*KP + seg*4), Kb + (size_t)(kt + r)*DK + seg*4);
    }
    #pragma unroll
    for (int p = 0; p < 5; p++) {
        int c = tid + p*256;
        int r = c / 20, seg = c % 20;
        cp16(smem_u32(sV + r*VP + seg*4), Vb + (size_t)(kt + r)*DK + seg*4);
    }
    cp_commit();
}

__global__ __launch_bounds__(256) void attn_kernel()
{
    extern __shared__ float sm[];
    float* sQ = sm + OFF_Q;       // also sP after qa caching
    float* sP = sm + OFF_Q;

    const int b = blockIdx.z, h = blockIdx.y, q0 = blockIdx.x * 128;
    const int tid = threadIdx.x;
    const int warp = tid >> 5, lane = tid & 31;
    const int g = lane >> 2, t = lane & 3;
    const int wr = warp * 16;

    const size_t base = ((size_t)b*NH + h) * SS * DK;
    const float* Qb = g_q + base;
    const float* Kb = g_k + base;
    const float* Vb = g_v + base;

    const float scl = rsqrtf((float)DK);

    // stage Q (scaled, rna, column-paired) + kick off tile 0 loads
    for (int i = tid; i < 128*DK; i += 256) {
        int r = i / DK, k = i % DK;
        sQ[r*QP + perm8(k)] = f2tf32(Qb[(size_t)(q0 + r)*DK + k] * scl);
    }
    attn_issue(Kb, Vb, sm + OFF_K, sm + OFF_V, 0, tid);
    __syncthreads();

    // cache Q A-fragments (float2 paired loads)
    unsigned qa[10][4];
    #pragma unroll
    for (int ks = 0; ks < 10; ks++) {
        float2 qlo = *(const float2*)&sQ[(wr + g    )*QP + ks*8 + 2*t];
        float2 qhi = *(const float2*)&sQ[(wr + g + 8)*QP + ks*8 + 2*t];
        qa[ks][0] = __float_as_uint(qlo.x);
        qa[ks][2] = __float_as_uint(qlo.y);
        qa[ks][1] = __float_as_uint(qhi.x);
        qa[ks][3] = __float_as_uint(qhi.y);
    }

    float O[10][4];
    #pragma unroll
    for (int nt = 0; nt < 10; nt++)
        #pragma unroll
        for (int j = 0; j < 4; j++) O[nt][j] = 0.f;
    float m0 = -1e30f, m1 = -1e30f, l0 = 0.f, l1 = 0.f;

    const int pc0 = ((2*t & 3) << 1) | ((2*t) >> 2);
    const int pc1 = (((2*t+1) & 3) << 1) | ((2*t+1) >> 2);

    for (int tt = 0; tt < SS/64; tt++) {
        float* sK = sm + OFF_K + (tt & 1) * 64*KP;
        float* sV = sm + OFF_V + (tt & 1) * 64*VP;

        if (tt + 1 < SS/64) {
            attn_issue(Kb, Vb, sm + OFF_K + ((tt+1)&1)*64*KP,
                       sm + OFF_V + ((tt+1)&1)*64*VP, (tt+1)*64, tid);
            cp_wait<1>();
        } else {
            cp_wait<0>();
        }
        __syncthreads();

        // ---- scores (raw fp32 K bits -> tf32 truncation; K pre-rounded rna) ----
        float sc[8][4];
        #pragma unroll
        for (int nt = 0; nt < 8; nt++)
            #pragma unroll
            for (int j = 0; j < 4; j++) sc[nt][j] = 0.f;

        #pragma unroll
        for (int ks = 0; ks < 10; ks++) {
            #pragma unroll
            for (int nt = 0; nt < 8; nt++) {
                unsigned bb[2];
                bb[0] = __float_as_uint(sK[(nt*8 + g)*KP + ks*8 + t    ]);
                bb[1] = __float_as_uint(sK[(nt*8 + g)*KP + ks*8 + t + 4]);
                mma_tf32(sc[nt], qa[ks], bb);
            }
        }

        // ---- online softmax ----
        float mx0 = -1e30f, mx1 = -1e30f;
        #pragma unroll
        for (int nt = 0; nt < 8; nt++) {
            mx0 = fmaxf(mx0, fmaxf(sc[nt][0], sc[nt][1]));
            mx1 = fmaxf(mx1, fmaxf(sc[nt][2], sc[nt][3]));
        }
        #pragma unroll
        for (int msk = 1; msk <= 2; msk <<= 1) {
            mx0 = fmaxf(mx0, __shfl_xor_sync(0xffffffffu, mx0, msk));
            mx1 = fmaxf(mx1, __shfl_xor_sync(0xffffffffu, mx1, msk));
        }
        float mn0 = fmaxf(m0, mx0), mn1 = fmaxf(m1, mx1);
        float a0 = __expf(m0 - mn0), a1 = __expf(m1 - mn1);
        m0 = mn0; m1 = mn1;

        float sum0 = 0.f, sum1 = 0.f;
        #pragma unroll
        for (int nt = 0; nt < 8; nt++) {
            sc[nt][0] = __expf(sc[nt][0] - m0);
            sc[nt][1] = __expf(sc[nt][1] - m0);
            sc[nt][2] = __expf(sc[nt][2] - m1);
            sc[nt][3] = __expf(sc[nt][3] - m1);
            sum0 += sc[nt][0] + sc[nt][1];
            sum1 += sc[nt][2] + sc[nt][3];
        }
        #pragma unroll
        for (int msk = 1; msk <= 2; msk <<= 1) {
            sum0 += __shfl_xor_sync(0xffffffffu, sum0, msk);
            sum1 += __shfl_xor_sync(0xffffffffu, sum1, msk);
        }
        l0 = l0*a0 + sum0;
        l1 = l1*a1 + sum1;

        #pragma unroll
        for (int nt = 0; nt < 10; nt++) {
            O[nt][0] *= a0; O[nt][1] *= a0;
            O[nt][2] *= a1; O[nt][3] *= a1;
        }

        // ---- stage P (warp-private rows, rna-rounded, paired cols) ----
        #pragma unroll
        for (int nt = 0; nt < 8; nt++) {
            sP[(wr + g    )*QP + nt*8 + pc0] = f2tf32(sc[nt][0]);
            sP[(wr + g    )*QP + nt*8 + pc1] = f2tf32(sc[nt][1]);
            sP[(wr + g + 8)*QP + nt*8 + pc0] = f2tf32(sc[nt][2]);
            sP[(wr + g + 8)*QP + nt*8 + pc1] = f2tf32(sc[nt][3]);
        }
        __syncwarp();

        // ---- PV: O(16x80) += P(16x64) @ V(64x80) ----
        #pragma unroll
        for (int ks = 0; ks < 8; ks++) {
            float2 plo = *(const float2*)&sP[(wr + g    )*QP + ks*8 + 2*t];
            float2 phi = *(const float2*)&sP[(wr + g + 8)*QP + ks*8 + 2*t];
            unsigned pa[4];
            pa[0] = __float_as_uint(plo.x);
            pa[2] = __float_as_uint(plo.y);
            pa[1] = __float_as_uint(phi.x);
            pa[3] = __float_as_uint(phi.y);
            #pragma unroll
            for (int nt = 0; nt < 10; nt++) {
                unsigned bb[2];
                bb[0] = __float_as_uint(sV[(ks*8 + t    )*VP + nt*8 + g]);
                bb[1] = __float_as_uint(sV[(ks*8 + t + 4)*VP + nt*8 + g]);
                mma_tf32(O[nt], pa, bb);
            }
        }
        __syncthreads();   // all warps done with this K/V buffer
    }

    // ---- epilogue ----
    float inv0 = 1.f / l0, inv1 = 1.f / l1;
    int s0r = q0 + wr + g, s1r = s0r + 8;
    #pragma unroll
    for (int nt = 0; nt < 10; nt++) {
        int c = nt*8 + 2*t;
        float2 v0 = make_float2(O[nt][0]*inv0, O[nt][1]*inv0);
        float2 v1 = make_float2(O[nt][2]*inv1, O[nt][3]*inv1);
        *(float2*)&g_att[((size_t)b*SS + s0r)*DM + h*DK + c] = v0;
        *(float2*)&g_att[((size_t)b*SS + s1r)*DM + h*DK + c] = v1;
    }
}

// ============================================================
// Kernel 3: out = g_att @ Wo^T + bo
// cp.async double-buffered, on-the-fly 3xTF32 split
// 128x128 tiles, k-chunks of 16, stride 20 (conflict-free)
// ============================================================
#define GST 20
#define GEMM_SMEM_FLOATS (4 * 128 * GST)

__device__ __forceinline__ void gemm_issue(const float* A, const float* B,
                                           float* sA, float* sB,
                                           int m0, int n0, int k0, int tid)
{
    #pragma unroll
    for (int p = 0; p < 2; p++) {
        int c = tid + p*256;
        int r = c >> 2, seg = c & 3;
        cp16(smem_u32(sA + r*GST + seg*4), A + (size_t)(m0 + r)*DM + k0 + seg*4);
        cp16(smem_u32(sB + r*GST + seg*4), B + (size_t)(n0 + r)*DM + k0 + seg*4);
    }
    cp_commit();
}

__global__ __launch_bounds__(256, 2) void out_gemm(
    const float* __restrict__ Wo, const float* __restrict__ bo,
    float* __restrict__ out)
{
    extern __shared__ float gsm[];
    float* sAb[2] = {gsm, gsm + 128*GST};
    float* sBb[2] = {gsm + 2*128*GST, gsm + 3*128*GST};

    const int m0 = blockIdx.y * 128, n0 = blockIdx.x * 128;
    const int tid = threadIdx.x;
    const int warp = tid >> 5, lane = tid & 31;
    const int g = lane >> 2, t = lane & 3;
    const int wm = warp >> 2, wn = warp & 3;

    float acc[4][4][4];
    #pragma unroll
    for (int mt = 0; mt < 4; mt++)
        #pragma unroll
        for (int nt = 0; nt < 4; nt++)
            #pragma unroll
            for (int j = 0; j < 4; j++) acc[mt][nt][j] = 0.f;

    gemm_issue(g_att, Wo, sAb[0], sBb[0], m0, n0, 0, tid);

    for (int kc = 0; kc < DM/16; kc++) {
        if (kc + 1 < DM/16) {
            gemm_issue(g_att, Wo, sAb[(kc+1)&1], sBb[(kc+1)&1], m0, n0, (kc+1)*16, tid);
            cp_wait<1>();
        } else {
            cp_wait<0>();
        }
        __syncthreads();

        const float* sA = sAb[kc & 1];
        const float* sB = sBb[kc & 1];

        #pragma unroll
        for (int kk = 0; kk < 2; kk++) {
            unsigned bh[4][2], bl[4][2];
            #pragma unroll
            for (int nt = 0; nt < 4; nt++) {
                int nrow = wn*32 + nt*8 + g;
                float b0 = sB[nrow*GST + kk*8 + t    ];
                float b1 = sB[nrow*GST + kk*8 + t + 4];
                float b0h = f2tf32(b0), b1h = f2tf32(b1);
                bh[nt][0] = __float_as_uint(b0h);
                bh[nt][1] = __float_as_uint(b1h);
                bl[nt][0] = __float_as_uint(b0 - b0h);
                bl[nt][1] = __float_as_uint(b1 - b1h);
            }
            #pragma unroll
            for (int mt = 0; mt < 4; mt++) {
                int mrow = wm*64 + mt*16;
                float a0 = sA[(mrow + g    )*GST + kk*8 + t    ];
                float a1 = sA[(mrow + g + 8)*GST + kk*8 + t    ];
                float a2 = sA[(mrow + g    )*GST + kk*8 + t + 4];
                float a3 = sA[(mrow + g + 8)*GST + kk*8 + t + 4];
                float a0h = f2tf32(a0), a1h = f2tf32(a1);
                float a2h = f2tf32(a2), a3h = f2tf32(a3);
                unsigned ah[4] = {__float_as_uint(a0h), __float_as_uint(a1h),
                                  __float_as_uint(a2h), __float_as_uint(a3h)};
                unsigned al[4] = {__float_as_uint(a0 - a0h), __float_as_uint(a1 - a1h),
                                  __float_as_uint(a2 - a2h), __float_as_uint(a3 - a3h)};
                #pragma unroll
                for (int nt = 0; nt < 4; nt++) {
                    mma_tf32(acc[mt][nt], ah, bh[nt]);
                    mma_tf32(acc[mt][nt], ah, bl[nt]);
                    mma_tf32(acc[mt][nt], al, bh[nt]);
                }
            }
        }
        __syncthreads();
    }

    #pragma unroll
    for (int mt = 0; mt < 4; mt++) {
        int r0 = m0 + wm*64 + mt*16 + g;
        #pragma unroll
        for (int nt = 0; nt < 4; nt++) {
            int c0 = n0 + wn*32 + nt*8 + 2*t;
            float2 b2 = *(const float2*)&bo[c0];
            float2 v0 = make_float2(acc[mt][nt][0] + b2.x, acc[mt][nt][1] + b2.y);
            float2 v1 = make_float2(acc[mt][nt][2] + b2.x, acc[mt][nt][3] + b2.y);
            *(float2*)&out[(size_t)r0*DM + c0] = v0;
            *(float2*)&out[(size_t)(r0 + 8)*DM + c0] = v1;
        }
    }
}

// ============================================================
extern "C" void kernel_launch(void* const* d_in, const int* in_sizes, int n_in,
                              void* d_out, int out_size)
{
    const float* src = (const float*)d_in[0];
    const float* Wq = (const float*)d_in[3];
    const float* bq = (const float*)d_in[4];
    const float* Wk = (const float*)d_in[5];
    const float* bk = (const float*)d_in[6];
    const float* Wv = (const float*)d_in[7];
    const float* bv = (const float*)d_in[8];
    const float* Wo = (const float*)d_in[9];
    const float* bo = (const float*)d_in[10];
    float* out = (float*)d_out;

    const int smem_qkv  = (DK*132 + DK*84 + DK) * (int)sizeof(float);
    const int smem_attn = ATTN_SMEM_FLOATS * (int)sizeof(float);
    const int smem_gemm = GEMM_SMEM_FLOATS * (int)sizeof(float);
    cudaFuncSetAttribute(qkv_kernel, cudaFuncAttributeMaxDynamicSharedMemorySize, smem_qkv);
    cudaFuncSetAttribute(attn_kernel, cudaFuncAttributeMaxDynamicSharedMemorySize, smem_attn);
    cudaFuncSetAttribute(out_gemm, cudaFuncAttributeMaxDynamicSharedMemorySize, smem_gemm);

    qkv_kernel<<<dim3(SS/128, NH, BB), 256, smem_qkv>>>(src, Wq, bq, Wk, bk, Wv, bv);
    attn_kernel<<<dim3(SS/128, NH, BB), 256, smem_attn>>>();
    out_gemm<<<dim3(DM/128, (BB*SS)/128), 256, smem_gemm>>>(Wo, bo, out);
}

// round 5
// speedup vs baseline: 4.8875x; 1.4598x over previous
#include <cuda_runtime.h>
#include <math.h>

#define BB 4
#define SS 1024
#define DM 1280
#define NH 16
#define DK 80
#define GR 5
#define CPG 256

// ---- scratch (device globals; no allocations allowed) ----
__device__ float g_q[(size_t)BB*NH*SS*DK];
__device__ float g_k[(size_t)BB*NH*SS*DK];
__device__ float g_v[(size_t)BB*NH*SS*DK];
__device__ float g_att[(size_t)BB*SS*DM];

// ---- helpers ----
__device__ __forceinline__ float f2tf32(float x) {
    unsigned u;
    asm("cvt.rna.tf32.f32 %0, %1;" : "=r"(u) : "f"(x));
    return __uint_as_float(u);
}
__device__ __forceinline__ void mma_tf32(float d[4], const unsigned a[4], const unsigned b[2]) {
    asm volatile(
        "mma.sync.aligned.m16n8k8.row.col.f32.tf32.tf32.f32 "
        "{%0,%1,%2,%3}, {%4,%5,%6,%7}, {%8,%9}, {%0,%1,%2,%3};\n"
        : "+f"(d[0]), "+f"(d[1]), "+f"(d[2]), "+f"(d[3])
        : "r"(a[0]), "r"(a[1]), "r"(a[2]), "r"(a[3]), "r"(b[0]), "r"(b[1]));
}
__device__ __forceinline__ void mma_bf16(float d[4], const unsigned a[4], const unsigned b[2]) {
    asm volatile(
        "mma.sync.aligned.m16n8k16.row.col.f32.bf16.bf16.f32 "
        "{%0,%1,%2,%3}, {%4,%5,%6,%7}, {%8,%9}, {%0,%1,%2,%3};\n"
        : "+f"(d[0]), "+f"(d[1]), "+f"(d[2]), "+f"(d[3])
        : "r"(a[0]), "r"(a[1]), "r"(a[2]), "r"(a[3]), "r"(b[0]), "r"(b[1]));
}
__device__ __forceinline__ unsigned pack_bf16(float hi, float lo) {
    unsigned r;
    asm("cvt.rn.bf16x2.f32 %0, %1, %2;" : "=r"(r) : "f"(hi), "f"(lo));
    return r;
}
__device__ __forceinline__ float bf_lo(unsigned w) { return __uint_as_float(w << 16); }
__device__ __forceinline__ float bf_hi(unsigned w) { return __uint_as_float(w & 0xffff0000u); }

__device__ __forceinline__ unsigned smem_u32(const void* p) {
    return (unsigned)__cvta_generic_to_shared(p);
}
__device__ __forceinline__ void cp16(unsigned s, const void* g) {
    asm volatile("cp.async.cg.shared.global [%0], [%1], 16;" :: "r"(s), "l"(g));
}
__device__ __forceinline__ void cp_commit() { asm volatile("cp.async.commit_group;"); }
template<int N> __device__ __forceinline__ void cp_wait() {
    asm volatile("cp.async.wait_group %0;" :: "n"(N));
}
// column pairing within 8-group: (t, t+4) -> adjacent (2t, 2t+1)
__device__ __forceinline__ int perm8(int c) {
    return (c & ~7) | ((c & 3) << 1) | ((c >> 2) & 1);
}

// ============================================================
// Kernel 1: channel shuffle + per-head QKV projections
// tf32 mma.sync: block 256 = 8 warps x 16 rows, 128-row tiles
// X staged straight [r][k] (stride 84), W [e][k] (stride 84),
// both rna-rounded to tf32 at staging. Q A-frags cached once.
// ============================================================
#define XS 84
#define QKV_SMEM_FLOATS (128*XS + 80*XS + 80)

__global__ __launch_bounds__(256) void qkv_kernel(
    const float* __restrict__ src,
    const float* __restrict__ Wq, const float* __restrict__ bq,
    const float* __restrict__ Wk, const float* __restrict__ bk,
    const float* __restrict__ Wv, const float* __restrict__ bv)
{
    extern __shared__ float qsm[];
    float* sX = qsm;              // [128][84]
    float* sW = sX + 128*XS;      // [80][84]
    float* sb = sW + 80*XS;       // [80]

    const int b = blockIdx.z, h = blockIdx.y, s0 = blockIdx.x * 128;
    const int tid = threadIdx.x;
    const int warp = tid >> 5, lane = tid & 31;
    const int g = lane >> 2, t = lane & 3;
    const int wr = warp * 16;

    // stage X: shuffle gather, per row 5 contiguous 16-float segments
    // column in src = j*256 + 16h + i  <->  k = i*5 + j
    #pragma unroll
    for (int p = 0; p < 10; p++) {
        int idx = tid + p*256;              // 2560 float4 pieces
        int r = idx / 20, q = idx % 20;
        int j = q / 4, m = q % 4;           // segment j, piece m (i = 4m..4m+3)
        float4 v = *(const float4*)&src[((size_t)b*SS + s0 + r)*DM + j*CPG + 16*h + m*4];
        int kbase = (m*4)*5 + j;
        sX[r*XS + kbase     ] = f2tf32(v.x);
        sX[r*XS + kbase + 5 ] = f2tf32(v.y);
        sX[r*XS + kbase + 10] = f2tf32(v.z);
        sX[r*XS + kbase + 15] = f2tf32(v.w);
    }
    __syncthreads();

    // cache X A-fragments once (shared by all 3 projections)
    unsigned qa[10][4];
    #pragma unroll
    for (int ks = 0; ks < 10; ks++) {
        qa[ks][0] = __float_as_uint(sX[(wr + g    )*XS + ks*8 + t    ]);
        qa[ks][1] = __float_as_uint(sX[(wr + g + 8)*XS + ks*8 + t    ]);
        qa[ks][2] = __float_as_uint(sX[(wr + g    )*XS + ks*8 + t + 4]);
        qa[ks][3] = __float_as_uint(sX[(wr + g + 8)*XS + ks*8 + t + 4]);
    }

    const float* Ws[3] = {Wq, Wk, Wv};
    const float* bs[3] = {bq, bk, bv};
    float* outs[3] = {g_q, g_k, g_v};

    for (int pj = 0; pj < 3; pj++) {
        __syncthreads();   // prev projection done reading sW
        for (int i = tid; i < 1600; i += 256) {
            int e = i / 20, k = (i % 20) * 4;
            float4 w = *(const float4*)&Ws[pj][h*DK*DK + e*DK + k];
            float4 wr4 = make_float4(f2tf32(w.x), f2tf32(w.y), f2tf32(w.z), f2tf32(w.w));
            *(float4*)&sW[e*XS + k] = wr4;
        }
        if (tid < DK) sb[tid] = bs[pj][h*DK + tid];
        __syncthreads();

        float acc[10][4];
        #pragma unroll
        for (int nt = 0; nt < 10; nt++)
            #pragma unroll
            for (int j = 0; j < 4; j++) acc[nt][j] = 0.f;

        #pragma unroll
        for (int ks = 0; ks < 10; ks++) {
            #pragma unroll
            for (int nt = 0; nt < 10; nt++) {
                unsigned bb[2];
                bb[0] = __float_as_uint(sW[(nt*8 + g)*XS + ks*8 + t    ]);
                bb[1] = __float_as_uint(sW[(nt*8 + g)*XS + ks*8 + t + 4]);
                mma_tf32(acc[nt], qa[ks], bb);
            }
        }

        float* outp = outs[pj] + (((size_t)b*NH + h)*SS + s0) * DK;
        #pragma unroll
        for (int nt = 0; nt < 10; nt++) {
            int c = nt*8 + 2*t;
            float b0 = sb[c], b1 = sb[c + 1];
            float2 v0 = make_float2(f2tf32(acc[nt][0] + b0), f2tf32(acc[nt][1] + b1));
            float2 v1 = make_float2(f2tf32(acc[nt][2] + b0), f2tf32(acc[nt][3] + b1));
            *(float2*)&outp[(size_t)(wr + g    )*DK + c] = v0;
            *(float2*)&outp[(size_t)(wr + g + 8)*DK + c] = v1;
        }
    }
}

// ============================================================
// Kernel 2: flash attention, tf32 mma, cp.async double-buffered
// (unchanged from round 4)
// ============================================================
#define QP 88
#define KP 84
#define VP 88
#define OFF_Q 0
#define OFF_K (128*QP)
#define OFF_V (OFF_K + 2*64*KP)
#define ATTN_SMEM_FLOATS (OFF_V + 2*64*VP)

__device__ __forceinline__ void attn_issue(const float* Kb, const float* Vb,
                                           float* sK, float* sV, int kt, int tid)
{
    #pragma unroll
    for (int p = 0; p < 5; p++) {
        int c = tid + p*256;
        int r = c / 20, seg = c % 20;
        cp16(smem_u32(sK + r*KP + seg*4), Kb + (size_t)(kt + r)*DK + seg*4);
    }
    #pragma unroll
    for (int p = 0; p < 5; p++) {
        int c = tid + p*256;
        int r = c / 20, seg = c % 20;
        cp16(smem_u32(sV + r*VP + seg*4), Vb + (size_t)(kt + r)*DK + seg*4);
    }
    cp_commit();
}

__global__ __launch_bounds__(256) void attn_kernel()
{
    extern __shared__ float sm[];
    float* sQ = sm + OFF_Q;       // also sP after qa caching
    float* sP = sm + OFF_Q;

    const int b = blockIdx.z, h = blockIdx.y, q0 = blockIdx.x * 128;
    const int tid = threadIdx.x;
    const int warp = tid >> 5, lane = tid & 31;
    const int g = lane >> 2, t = lane & 3;
    const int wr = warp * 16;

    const size_t base = ((size_t)b*NH + h) * SS * DK;
    const float* Qb = g_q + base;
    const float* Kb = g_k + base;
    const float* Vb = g_v + base;

    const float scl = rsqrtf((float)DK);

    for (int i = tid; i < 128*DK; i += 256) {
        int r = i / DK, k = i % DK;
        sQ[r*QP + perm8(k)] = f2tf32(Qb[(size_t)(q0 + r)*DK + k] * scl);
    }
    attn_issue(Kb, Vb, sm + OFF_K, sm + OFF_V, 0, tid);
    __syncthreads();

    unsigned qa[10][4];
    #pragma unroll
    for (int ks = 0; ks < 10; ks++) {
        float2 qlo = *(const float2*)&sQ[(wr + g    )*QP + ks*8 + 2*t];
        float2 qhi = *(const float2*)&sQ[(wr + g + 8)*QP + ks*8 + 2*t];
        qa[ks][0] = __float_as_uint(qlo.x);
        qa[ks][2] = __float_as_uint(qlo.y);
        qa[ks][1] = __float_as_uint(qhi.x);
        qa[ks][3] = __float_as_uint(qhi.y);
    }

    float O[10][4];
    #pragma unroll
    for (int nt = 0; nt < 10; nt++)
        #pragma unroll
        for (int j = 0; j < 4; j++) O[nt][j] = 0.f;
    float m0 = -1e30f, m1 = -1e30f, l0 = 0.f, l1 = 0.f;

    const int pc0 = ((2*t & 3) << 1) | ((2*t) >> 2);
    const int pc1 = (((2*t+1) & 3) << 1) | ((2*t+1) >> 2);

    for (int tt = 0; tt < SS/64; tt++) {
        float* sK = sm + OFF_K + (tt & 1) * 64*KP;
        float* sV = sm + OFF_V + (tt & 1) * 64*VP;

        if (tt + 1 < SS/64) {
            attn_issue(Kb, Vb, sm + OFF_K + ((tt+1)&1)*64*KP,
                       sm + OFF_V + ((tt+1)&1)*64*VP, (tt+1)*64, tid);
            cp_wait<1>();
        } else {
            cp_wait<0>();
        }
        __syncthreads();

        float sc[8][4];
        #pragma unroll
        for (int nt = 0; nt < 8; nt++)
            #pragma unroll
            for (int j = 0; j < 4; j++) sc[nt][j] = 0.f;

        #pragma unroll
        for (int ks = 0; ks < 10; ks++) {
            #pragma unroll
            for (int nt = 0; nt < 8; nt++) {
                unsigned bb[2];
                bb[0] = __float_as_uint(sK[(nt*8 + g)*KP + ks*8 + t    ]);
                bb[1] = __float_as_uint(sK[(nt*8 + g)*KP + ks*8 + t + 4]);
                mma_tf32(sc[nt], qa[ks], bb);
            }
        }

        float mx0 = -1e30f, mx1 = -1e30f;
        #pragma unroll
        for (int nt = 0; nt < 8; nt++) {
            mx0 = fmaxf(mx0, fmaxf(sc[nt][0], sc[nt][1]));
            mx1 = fmaxf(mx1, fmaxf(sc[nt][2], sc[nt][3]));
        }
        #pragma unroll
        for (int msk = 1; msk <= 2; msk <<= 1) {
            mx0 = fmaxf(mx0, __shfl_xor_sync(0xffffffffu, mx0, msk));
            mx1 = fmaxf(mx1, __shfl_xor_sync(0xffffffffu, mx1, msk));
        }
        float mn0 = fmaxf(m0, mx0), mn1 = fmaxf(m1, mx1);
        float a0 = __expf(m0 - mn0), a1 = __expf(m1 - mn1);
        m0 = mn0; m1 = mn1;

        float sum0 = 0.f, sum1 = 0.f;
        #pragma unroll
        for (int nt = 0; nt < 8; nt++) {
            sc[nt][0] = __expf(sc[nt][0] - m0);
            sc[nt][1] = __expf(sc[nt][1] - m0);
            sc[nt][2] = __expf(sc[nt][2] - m1);
            sc[nt][3] = __expf(sc[nt][3] - m1);
            sum0 += sc[nt][0] + sc[nt][1];
            sum1 += sc[nt][2] + sc[nt][3];
        }
        #pragma unroll
        for (int msk = 1; msk <= 2; msk <<= 1) {
            sum0 += __shfl_xor_sync(0xffffffffu, sum0, msk);
            sum1 += __shfl_xor_sync(0xffffffffu, sum1, msk);
        }
        l0 = l0*a0 + sum0;
        l1 = l1*a1 + sum1;

        #pragma unroll
        for (int nt = 0; nt < 10; nt++) {
            O[nt][0] *= a0; O[nt][1] *= a0;
            O[nt][2] *= a1; O[nt][3] *= a1;
        }

        #pragma unroll
        for (int nt = 0; nt < 8; nt++) {
            sP[(wr + g    )*QP + nt*8 + pc0] = f2tf32(sc[nt][0]);
            sP[(wr + g    )*QP + nt*8 + pc1] = f2tf32(sc[nt][1]);
            sP[(wr + g + 8)*QP + nt*8 + pc0] = f2tf32(sc[nt][2]);
            sP[(wr + g + 8)*QP + nt*8 + pc1] = f2tf32(sc[nt][3]);
        }
        __syncwarp();

        #pragma unroll
        for (int ks = 0; ks < 8; ks++) {
            float2 plo = *(const float2*)&sP[(wr + g    )*QP + ks*8 + 2*t];
            float2 phi = *(const float2*)&sP[(wr + g + 8)*QP + ks*8 + 2*t];
            unsigned pa[4];
            pa[0] = __float_as_uint(plo.x);
            pa[2] = __float_as_uint(plo.y);
            pa[1] = __float_as_uint(phi.x);
            pa[3] = __float_as_uint(phi.y);
            #pragma unroll
            for (int nt = 0; nt < 10; nt++) {
                unsigned bb[2];
                bb[0] = __float_as_uint(sV[(ks*8 + t    )*VP + nt*8 + g]);
                bb[1] = __float_as_uint(sV[(ks*8 + t + 4)*VP + nt*8 + g]);
                mma_tf32(O[nt], pa, bb);
            }
        }
        __syncthreads();
    }

    float inv0 = 1.f / l0, inv1 = 1.f / l1;
    int s0r = q0 + wr + g, s1r = s0r + 8;
    #pragma unroll
    for (int nt = 0; nt < 10; nt++) {
        int c = nt*8 + 2*t;
        float2 v0 = make_float2(O[nt][0]*inv0, O[nt][1]*inv0);
        float2 v1 = make_float2(O[nt][2]*inv1, O[nt][3]*inv1);
        *(float2*)&g_att[((size_t)b*SS + s0r)*DM + h*DK + c] = v0;
        *(float2*)&g_att[((size_t)b*SS + s1r)*DM + h*DK + c] = v1;
    }
}

// ============================================================
// Kernel 3: out = g_att @ Wo^T + bo, bf16 3-term split
// (ah*bh + ah*bl + al*bh), m16n8k16, packed bf16x2 smem words,
// register prefetch + split at stage time, 1 barrier per chunk
// ============================================================
#define GWS 12                       // u32 stride per row (8 words + pad)
#define GBUF (128*GWS)               // one part, one buffer
#define GEMM_SMEM_U32 (8*GBUF)       // {Ah,Al,Bh,Bl} x 2 buffers

__global__ __launch_bounds__(256, 2) void out_gemm(
    const float* __restrict__ Wo, const float* __restrict__ bo,
    float* __restrict__ out)
{
    extern __shared__ unsigned gsm[];
    unsigned* AH = gsm;
    unsigned* AL = gsm + 2*GBUF;
    unsigned* BH = gsm + 4*GBUF;
    unsigned* BL = gsm + 6*GBUF;

    const int m0 = blockIdx.y * 128, n0 = blockIdx.x * 128;
    const int tid = threadIdx.x;
    const int warp = tid >> 5, lane = tid & 31;
    const int g = lane >> 2, t = lane & 3;
    const int wm = warp >> 2, wn = warp & 3;

    // staging coords: thread covers rows ar0/ar1, 4 consecutive k at ac
    const int ar0 = tid >> 2, ar1 = (tid + 256) >> 2;
    const int ac = (tid & 3) * 4;
    const int w0 = (tid & 3) * 2;              // orig word index (0,2,4,6)
    const int pw0 = perm8(w0), pw1 = perm8(w0 + 1);

    float acc[4][4][4];
    #pragma unroll
    for (int mt = 0; mt < 4; mt++)
        #pragma unroll
        for (int nt = 0; nt < 4; nt++)
            #pragma unroll
            for (int j = 0; j < 4; j++) acc[mt][nt][j] = 0.f;

    float4 ra[2], rb[2];
    ra[0] = *(const float4*)&g_att[(size_t)(m0 + ar0)*DM + ac];
    ra[1] = *(const float4*)&g_att[(size_t)(m0 + ar1)*DM + ac];
    rb[0] = *(const float4*)&Wo[(size_t)(n0 + ar0)*DM + ac];
    rb[1] = *(const float4*)&Wo[(size_t)(n0 + ar1)*DM + ac];

    for (int kc = 0; kc < DM/16; kc++) {
        const int bs = kc & 1;
        unsigned* ah = AH + bs*GBUF;
        unsigned* al = AL + bs*GBUF;
        unsigned* bh = BH + bs*GBUF;
        unsigned* bl = BL + bs*GBUF;

        // split + store packed words
        #pragma unroll
        for (int p = 0; p < 2; p++) {
            int r = p ? ar1 : ar0;
            float4 va = ra[p], vb = rb[p];
            unsigned ha0 = pack_bf16(va.y, va.x);
            unsigned ha1 = pack_bf16(va.w, va.z);
            unsigned la0 = pack_bf16(va.y - bf_hi(ha0), va.x - bf_lo(ha0));
            unsigned la1 = pack_bf16(va.w - bf_hi(ha1), va.z - bf_lo(ha1));
            ah[r*GWS + pw0] = ha0;  ah[r*GWS + pw1] = ha1;
            al[r*GWS + pw0] = la0;  al[r*GWS + pw1] = la1;
            unsigned hb0 = pack_bf16(vb.y, vb.x);
            unsigned hb1 = pack_bf16(vb.w, vb.z);
            unsigned lb0 = pack_bf16(vb.y - bf_hi(hb0), vb.x - bf_lo(hb0));
            unsigned lb1 = pack_bf16(vb.w - bf_hi(hb1), vb.z - bf_lo(hb1));
            bh[r*GWS + pw0] = hb0;  bh[r*GWS + pw1] = hb1;
            bl[r*GWS + pw0] = lb0;  bl[r*GWS + pw1] = lb1;
        }

        // prefetch next chunk (overlaps barrier + MMA)
        if (kc + 1 < DM/16) {
            int k0n = (kc + 1) * 16;
            ra[0] = *(const float4*)&g_att[(size_t)(m0 + ar0)*DM + k0n + ac];
            ra[1] = *(const float4*)&g_att[(size_t)(m0 + ar1)*DM + k0n + ac];
            rb[0] = *(const float4*)&Wo[(size_t)(n0 + ar0)*DM + k0n + ac];
            rb[1] = *(const float4*)&Wo[(size_t)(n0 + ar1)*DM + k0n + ac];
        }
        __syncthreads();

        // B fragments
        unsigned fbh[4][2], fbl[4][2];
        #pragma unroll
        for (int nt = 0; nt < 4; nt++) {
            int br = wn*32 + nt*8 + g;
            uint2 xh = *(const uint2*)&bh[br*GWS + 2*t];
            uint2 xl = *(const uint2*)&bl[br*GWS + 2*t];
            fbh[nt][0] = xh.x; fbh[nt][1] = xh.y;
            fbl[nt][0] = xl.x; fbl[nt][1] = xl.y;
        }
        #pragma unroll
        for (int mt = 0; mt < 4; mt++) {
            int mr = wm*64 + mt*16 + g;
            uint2 alo = *(const uint2*)&ah[ mr     *GWS + 2*t];
            uint2 ahi = *(const uint2*)&ah[(mr + 8)*GWS + 2*t];
            uint2 llo = *(const uint2*)&al[ mr     *GWS + 2*t];
            uint2 lhi = *(const uint2*)&al[(mr + 8)*GWS + 2*t];
            unsigned fah[4] = {alo.x, ahi.x, alo.y, ahi.y};
            unsigned fal[4] = {llo.x, lhi.x, llo.y, lhi.y};
            #pragma unroll
            for (int nt = 0; nt < 4; nt++) {
                mma_bf16(acc[mt][nt], fah, fbh[nt]);
                mma_bf16(acc[mt][nt], fah, fbl[nt]);
                mma_bf16(acc[mt][nt], fal, fbh[nt]);
            }
        }
        // no trailing barrier: packed buffers are double-buffered and the
        // next iteration's barrier orders its stores against these reads
    }

    #pragma unroll
    for (int mt = 0; mt < 4; mt++) {
        int r0 = m0 + wm*64 + mt*16 + g;
        #pragma unroll
        for (int nt = 0; nt < 4; nt++) {
            int c0 = n0 + wn*32 + nt*8 + 2*t;
            float2 b2 = *(const float2*)&bo[c0];
            float2 v0 = make_float2(acc[mt][nt][0] + b2.x, acc[mt][nt][1] + b2.y);
            float2 v1 = make_float2(acc[mt][nt][2] + b2.x, acc[mt][nt][3] + b2.y);
            *(float2*)&out[(size_t)r0*DM + c0] = v0;
            *(float2*)&out[(size_t)(r0 + 8)*DM + c0] = v1;
        }
    }
}

// ============================================================
extern "C" void kernel_launch(void* const* d_in, const int* in_sizes, int n_in,
                              void* d_out, int out_size)
{
    const float* src = (const float*)d_in[0];
    const float* Wq = (const float*)d_in[3];
    const float* bq = (const float*)d_in[4];
    const float* Wk = (const float*)d_in[5];
    const float* bk = (const float*)d_in[6];
    const float* Wv = (const float*)d_in[7];
    const float* bv = (const float*)d_in[8];
    const float* Wo = (const float*)d_in[9];
    const float* bo = (const float*)d_in[10];
    float* out = (float*)d_out;

    const int smem_qkv  = QKV_SMEM_FLOATS * (int)sizeof(float);
    const int smem_attn = ATTN_SMEM_FLOATS * (int)sizeof(float);
    const int smem_gemm = GEMM_SMEM_U32 * (int)sizeof(unsigned);
    cudaFuncSetAttribute(qkv_kernel, cudaFuncAttributeMaxDynamicSharedMemorySize, smem_qkv);
    cudaFuncSetAttribute(attn_kernel, cudaFuncAttributeMaxDynamicSharedMemorySize, smem_attn);
    cudaFuncSetAttribute(out_gemm, cudaFuncAttributeMaxDynamicSharedMemorySize, smem_gemm);

    qkv_kernel<<<dim3(SS/128, NH, BB), 256, smem_qkv>>>(src, Wq, bq, Wk, bk, Wv, bv);
    attn_kernel<<<dim3(SS/128, NH, BB), 256, smem_attn>>>();
    out_gemm<<<dim3(DM/128, (BB*SS)/128), 256, smem_gemm>>>(Wo, bo, out);
}